// round 3
// baseline (speedup 1.0000x reference)
#include <cuda_runtime.h>
#include <math.h>

// ---------------------------------------------------------------------------
// FNO block: 4 x (truncated spectral conv + 1x1 conv + gelu)
// B=64, N=16384, C=32, MODES=16. All fp32, f32x2-packed FMA.
// ---------------------------------------------------------------------------
#define N_    16384
#define B_    64
#define C_    32
#define MODES 16
#define NSPLIT 8
#define PITCH 132

typedef unsigned long long u64;

// ------------------------------- scratch -----------------------------------
__device__ float g_buf[B_ * N_ * C_];            // 128 MiB ping buffer
__device__ float g_S[B_ * NSPLIT * MODES * C_ * 2];
__device__ float g_W[B_ * 62 * C_];
__device__ float g_bias[B_ * C_];
__device__ float g_twC[MODES * N_];              // cos(2 pi m n / N)
__device__ float g_twS[MODES * N_];              // sin(2 pi m n / N)
__device__ u64   g_twD[N_ * 32];                 // [n][2m+ri] = dup(cos/sin)

// ------------------------------ f32x2 helpers ------------------------------
__device__ __forceinline__ u64 f2fma(u64 a, u64 b, u64 c) {
    u64 d;
    asm("fma.rn.f32x2 %0,%1,%2,%3;" : "=l"(d) : "l"(a), "l"(b), "l"(c));
    return d;
}
__device__ __forceinline__ u64 f2add(u64 a, u64 b) {
    u64 d;
    asm("add.rn.f32x2 %0,%1,%2;" : "=l"(d) : "l"(a), "l"(b));
    return d;
}
__device__ __forceinline__ u64 pk2(float lo, float hi) {
    u64 d;
    asm("mov.b64 %0,{%1,%2};" : "=l"(d) : "f"(lo), "f"(hi));
    return d;
}
__device__ __forceinline__ float2 upk(u64 a) {
    float lo, hi;
    asm("mov.b64 {%0,%1},%2;" : "=f"(lo), "=f"(hi) : "l"(a));
    return make_float2(lo, hi);
}

__device__ __forceinline__ float gelu_f(float h) {
    // 0.5 h (1+tanh(z)) == h * sigmoid(2z),  2z = 1.59576912 h + 0.07135482 h^3
    float u = h * h;
    float y = h * fmaf(u, 0.0713548163f, 1.5957691216f);
    return __fdividef(h, 1.0f + __expf(-y));
}

// ------------------------------- init --------------------------------------
__global__ void k_init() {
    int idx = blockIdx.x * 256 + threadIdx.x;      // 0 .. 16*16384-1
    int m = idx >> 14;
    int n = idx & (N_ - 1);
    int r = (m * n) & (N_ - 1);
    float s, c;
    sincospif((float)r * (1.0f / 8192.0f), &s, &c);  // exact phase: pi*r/8192
    g_twC[idx] = c;
    g_twS[idx] = s;
    g_twD[n * 32 + 2 * m]     = pk2(c, c);
    g_twD[n * 32 + 2 * m + 1] = pk2(s, s);
}

// ----------------------- K1: partial forward DFT ---------------------------
// grid (NSPLIT, B), 256 threads. Warp w handles 256 consecutive n.
// lane: cg = l&3 (channels 8cg..8cg+7 -> 4 channel-pairs), pg = l>>2
// (parts 4pg..4pg+3 where part q = 2m+reim).
__global__ void __launch_bounds__(256) k_dft(const float* __restrict__ xext, int d) {
    const float* x = (d == 0) ? xext : g_buf;
    int sp = blockIdx.x, b = blockIdx.y;
    int t = threadIdx.x, w = t >> 5, l = t & 31;
    int cg = l & 3, pg = l >> 2;
    const float4* x4 = (const float4*)(x + ((size_t)b << 19));
    int n0 = sp * 2048 + w * 256;

    u64 acc[4][4];
#pragma unroll
    for (int i = 0; i < 4; i++)
#pragma unroll
        for (int j = 0; j < 4; j++) acc[i][j] = 0ull;

#pragma unroll 4
    for (int nn = 0; nn < 256; nn++) {
        int n = n0 + nn;
        float4 v0 = __ldg(&x4[(size_t)n * 8 + 2 * cg]);
        float4 v1 = __ldg(&x4[(size_t)n * 8 + 2 * cg + 1]);
        u64 xp[4];
        xp[0] = pk2(v0.x, v0.y);
        xp[1] = pk2(v0.z, v0.w);
        xp[2] = pk2(v1.x, v1.y);
        xp[3] = pk2(v1.z, v1.w);
        const u64* tw = &g_twD[(size_t)n * 32 + 4 * pg];
        ulonglong2 ta = *(const ulonglong2*)(tw);
        ulonglong2 tb = *(const ulonglong2*)(tw + 2);
        u64 tq[4] = {ta.x, ta.y, tb.x, tb.y};
#pragma unroll
        for (int i = 0; i < 4; i++)
#pragma unroll
            for (int j = 0; j < 4; j++) acc[i][j] = f2fma(xp[j], tq[i], acc[i][j]);
    }

    // block reduction over the 8 warps (fixed order -> deterministic)
    __shared__ u64 red[8][512];
#pragma unroll
    for (int i = 0; i < 4; i++)
#pragma unroll
        for (int j = 0; j < 4; j++) red[w][l * 16 + i * 4 + j] = acc[i][j];
    __syncthreads();

    for (int s = t; s < 512; s += 256) {
        u64 a = red[0][s];
#pragma unroll
        for (int w2 = 1; w2 < 8; w2++) a = f2add(a, red[w2][s]);
        int lane = s >> 4, k = s & 15, i = k >> 2, j = k & 3;
        int q  = 4 * (lane >> 2) + i;
        int cp = 4 * (lane & 3) + j;
        int m = q >> 1, reim = q & 1;
        float2 f = upk(a);
        float sg = reim ? -1.0f : 1.0f;   // Im(X) = -sum x*sin
        size_t base = ((((size_t)b * NSPLIT + sp) * MODES + m) * C_ + 2 * cp);
        g_S[base * 2 + reim]       = sg * f.x;
        g_S[(base + 1) * 2 + reim] = sg * f.y;
    }
}

// --------------------- K2: mix + fused weight build ------------------------
__global__ void __launch_bounds__(512) k_mix(const float* __restrict__ Wr,
                                             const float* __restrict__ Wi,
                                             const float* __restrict__ ck,
                                             const float* __restrict__ cb, int d) {
    int b = blockIdx.x, t = threadIdx.x;
    int m = t >> 5, o = t & 31;
    __shared__ float xr[MODES][C_], xi[MODES][C_];
    {
        const float2* S2 = (const float2*)g_S;
        float re = 0.f, im = 0.f;
#pragma unroll
        for (int s = 0; s < NSPLIT; s++) {
            float2 v = S2[(((size_t)b * NSPLIT + s) * MODES + m) * C_ + o];
            re += v.x;
            im += v.y;
        }
        xr[m][o] = re;
        xi[m][o] = im;
    }
    __syncthreads();

    float oR = 0.f, oI = 0.f;
    const float* wr = Wr + (size_t)d * C_ * C_ * MODES;
    const float* wi = Wi + (size_t)d * C_ * C_ * MODES;
#pragma unroll 4
    for (int i = 0; i < C_; i++) {
        float a  = xr[m][i];
        float bi = xi[m][i];
        float r_ = wr[(i * C_ + o) * MODES + m];
        float q_ = wi[(i * C_ + o) * MODES + m];
        oR += a * r_ - bi * q_;
        oI += a * q_ + bi * r_;
    }
    float* Wb = g_W + (size_t)b * 62 * C_;
    if (m >= 1) {
        Wb[(m - 1) * C_ + o]  = oR * (2.0f / (float)N_);
        Wb[(14 + m) * C_ + o] = -oI * (2.0f / (float)N_);
    } else {
        g_bias[b * C_ + o] = oR * (1.0f / (float)N_) + cb[d * C_ + o];
    }
    for (int lin = t; lin < 1024; lin += 512) {
        int i = lin >> 5, oo = lin & 31;
        Wb[(30 + i) * C_ + oo] = ck[((size_t)d * C_ + i) * C_ + oo];
    }
}

// -------------- K3: fused inverse-eval + 1x1 conv + gelu -------------------
// grid (N/128, B), 128 threads. out[b,n,o] = gelu(A[n,:62] @ Wf[:,o] + bias)
__global__ void __launch_bounds__(128) k_out(const float* __restrict__ xext,
                                             float* __restrict__ oext, int d) {
    const float* xin = (d == 0) ? xext : g_buf;
    float* out       = (d == 3) ? oext : g_buf;
    int tile = blockIdx.x, b = blockIdx.y;
    int t = threadIdx.x;
    int n0 = tile << 7;

    __shared__ float  As[62 * PITCH];     // 32736 B
    __shared__ float2 W2s[62 * C_];       // 15872 B (pre-duplicated weights)
    __shared__ float  bs[C_];

    // trig rows 0..29
#pragma unroll
    for (int r = 0; r < 15; r++) As[r * PITCH + t] = g_twC[(r + 1) * N_ + n0 + t];
#pragma unroll
    for (int r = 15; r < 30; r++) As[r * PITCH + t] = g_twS[(r - 14) * N_ + n0 + t];
    // x rows 30..61 (transposed)
    const float4* x4 = (const float4*)(xin + ((size_t)b << 19));
#pragma unroll
    for (int k = 0; k < 8; k++) {
        int lin = k * 128 + t;
        int cq = lin & 7, nl = lin >> 3;
        float4 v = x4[(size_t)(n0 + nl) * 8 + cq];
        As[(30 + 4 * cq) * PITCH + nl] = v.x;
        As[(31 + 4 * cq) * PITCH + nl] = v.y;
        As[(32 + 4 * cq) * PITCH + nl] = v.z;
        As[(33 + 4 * cq) * PITCH + nl] = v.w;
    }
    const float* Wb = g_W + (size_t)b * 62 * C_;
    for (int lin = t; lin < 62 * C_; lin += 128) {
        float wv = Wb[lin];
        W2s[lin] = make_float2(wv, wv);
    }
    if (t < 32) bs[t] = g_bias[b * C_ + t];
    __syncthreads();

    int nq = t & 31, og = t >> 5;
    int nl = nq * 4, o0 = og * 8;
    u64 acc[16];
#pragma unroll
    for (int i = 0; i < 16; i++) acc[i] = 0ull;

    const float*  ap = As + nl;
    const float2* wp = W2s + o0;
#pragma unroll 2
    for (int r = 0; r < 62; r++) {
        ulonglong2 a = *(const ulonglong2*)(ap + r * PITCH);
#pragma unroll
        for (int j2 = 0; j2 < 4; j2++) {
            ulonglong2 w = *(const ulonglong2*)(wp + r * C_ + 2 * j2);
            acc[4 * j2 + 0] = f2fma(a.x, w.x, acc[4 * j2 + 0]);
            acc[4 * j2 + 1] = f2fma(a.y, w.x, acc[4 * j2 + 1]);
            acc[4 * j2 + 2] = f2fma(a.x, w.y, acc[4 * j2 + 2]);
            acc[4 * j2 + 3] = f2fma(a.y, w.y, acc[4 * j2 + 3]);
        }
    }

    float res[4][8];
#pragma unroll
    for (int j2 = 0; j2 < 4; j2++)
#pragma unroll
        for (int jj = 0; jj < 2; jj++) {
            int oj = 2 * j2 + jj;
            float bb = bs[o0 + oj];
#pragma unroll
            for (int p = 0; p < 2; p++) {
                float2 f = upk(acc[4 * j2 + 2 * jj + p]);
                res[2 * p + 0][oj] = gelu_f(f.x + bb);
                res[2 * p + 1][oj] = gelu_f(f.y + bb);
            }
        }

    float* op = out + (((size_t)b << 14) + n0 + nl) * C_ + o0;
#pragma unroll
    for (int nn = 0; nn < 4; nn++) {
        *(float4*)(op + nn * C_ + 0) = make_float4(res[nn][0], res[nn][1], res[nn][2], res[nn][3]);
        *(float4*)(op + nn * C_ + 4) = make_float4(res[nn][4], res[nn][5], res[nn][6], res[nn][7]);
    }
}

// ------------------------------- launch ------------------------------------
extern "C" void kernel_launch(void* const* d_in, const int* in_sizes, int n_in,
                              void* d_out, int out_size) {
    const float* x  = (const float*)d_in[0];
    const float* Wr = (const float*)d_in[1];
    const float* Wi = (const float*)d_in[2];
    const float* ck = (const float*)d_in[3];
    const float* cb = (const float*)d_in[4];
    float* out = (float*)d_out;

    k_init<<<(MODES * N_) / 256, 256>>>();
    for (int d = 0; d < 4; d++) {
        k_dft<<<dim3(NSPLIT, B_), 256>>>(x, d);
        k_mix<<<B_, 512>>>(Wr, Wi, ck, cb, d);
        k_out<<<dim3(N_ / 128, B_), 128>>>(x, out, d);
    }
}